// round 3
// baseline (speedup 1.0000x reference)
#include <cuda_runtime.h>

#define B_TOTAL 4096
#define V_TOTAL 1024
#define DD 64
#define TB 64
#define TV 64
#define NBLOCKS ((B_TOTAL / TB) * (V_TOTAL / TV))

// Zero-initialized scratch. Min stored as key = ~bits(value); dist >= 0 so bit
// order == value order, atomicMax(key) == min(value), and 0 is the identity.
// Last block resets to 0 -> graph-replay safe.
__device__ unsigned int g_rowmin_key[B_TOTAL];
__device__ unsigned int g_colmin_key[V_TOTAL];
__device__ unsigned int g_arrive;

typedef unsigned long long ull;

// acc += |a + b| (b pre-negated), packed f32x2; one asm region so the temp
// pair is allocated locally.
__device__ __forceinline__ void l1acc(ull& acc, ull a, ull b) {
    asm("{\n\t"
        ".reg .b64 d;\n\t"
        "add.rn.f32x2 d, %1, %2;\n\t"
        "and.b64 d, d, 0x7FFFFFFF7FFFFFFF;\n\t"
        "add.rn.f32x2 %0, %0, d;\n\t"
        "}"
        : "+l"(acc) : "l"(a), "l"(b));
}

__global__ __launch_bounds__(128, 7)
void dist_fused(const float* __restrict__ x, const float* __restrict__ p,
                float* __restrict__ out) {
    // 32768 B exactly: sm[0..2047] = x-tile pairs XS(kk,row)=sm[kk*64+row],
    //                  sm[2048..4095] = p-tile pairs PS(kk,v)=sm[2048+kk*64+v]
    // (k-pair-major; reduction scratch aliased in after the main loop)
    __shared__ ull sm[4096];

    const int tid = threadIdx.x;
    const int b0 = blockIdx.y * TB;
    const int v0 = blockIdx.x * TV;

    // ---- prologue: one row per thread; conflict-free STS.64 (lane rows
    // consecutive -> even-bank sweep), x rows walk sequentially (L1 reuse) ----
    if (tid < 64) {
        const float4* __restrict__ xr4 = (const float4*)(x + (size_t)(b0 + tid) * DD);
#pragma unroll
        for (int c4 = 0; c4 < 16; c4++) {
            float4 v = xr4[c4];
            int kk = c4 * 2;
            *(float2*)&sm[kk * 64 + tid]       = make_float2(v.x, v.y);
            *(float2*)&sm[(kk + 1) * 64 + tid] = make_float2(v.z, v.w);
        }
    } else {
        int r = tid - 64;
        const float4* __restrict__ pr4 = (const float4*)(p + (size_t)(v0 + r) * DD);
#pragma unroll
        for (int c4 = 0; c4 < 16; c4++) {
            float4 v = pr4[c4];
            int kk = c4 * 2;
            *(float2*)&sm[2048 + kk * 64 + r]       = make_float2(-v.x, -v.y);
            *(float2*)&sm[2048 + (kk + 1) * 64 + r] = make_float2(-v.z, -v.w);
        }
    }
    __syncthreads();

    const int tx = tid & 15;    // v = tx + 16*j
    const int ty = tid >> 4;    // b rows: ty*8 + i
    const int row0 = ty * 8;

    float cm[4];                // col-min partials carried across passes

    // ---- two column-passes: pass 0 -> j in {0,1}, pass 1 -> j in {2,3} ----
#pragma unroll 1
    for (int pass = 0; pass < 2; pass++) {
        const int jb = pass * 2;
        const int vA = tx + 16 * jb;
        const int vB = vA + 16;

        ull acc[8][2];
#pragma unroll
        for (int i = 0; i < 8; i++) { acc[i][0] = 0ull; acc[i][1] = 0ull; }

#pragma unroll 2
        for (int kk = 0; kk < 32; kk++) {
            ull pr0 = sm[2048 + kk * 64 + vA];   // 16 lanes -> 16 even banks
            ull pr1 = sm[2048 + kk * 64 + vB];
            ull xr[8];
#pragma unroll
            for (int i = 0; i < 8; i++)          // broadcast within 16-lane group
                xr[i] = sm[kk * 64 + row0 + i];
#pragma unroll
            for (int i = 0; i < 8; i++) {
                l1acc(acc[i][0], xr[i], pr0);
                l1acc(acc[i][1], xr[i], pr1);
            }
        }

        // horizontal pair sums
        float dist[8][2];
#pragma unroll
        for (int i = 0; i < 8; i++)
#pragma unroll
            for (int jj = 0; jj < 2; jj++) {
                ull a = acc[i][jj];
                float lo = __uint_as_float((unsigned)(a & 0xFFFFFFFFull));
                float hi = __uint_as_float((unsigned)(a >> 32));
                dist[i][jj] = lo + hi;
            }

        // write distances (lanes tx -> 64B coalesced segments)
#pragma unroll
        for (int i = 0; i < 8; i++) {
            size_t base = (size_t)(b0 + row0 + i) * V_TOTAL + v0;
            out[base + vA] = dist[i][0];
            out[base + vB] = dist[i][1];
        }

        // row mins for this pass (j pair), reduced over the 16 tx lanes
#pragma unroll
        for (int i = 0; i < 8; i++) {
            float rm = fminf(dist[i][0], dist[i][1]);
            rm = fminf(rm, __shfl_xor_sync(0xFFFFFFFFu, rm, 1));
            rm = fminf(rm, __shfl_xor_sync(0xFFFFFFFFu, rm, 2));
            rm = fminf(rm, __shfl_xor_sync(0xFFFFFFFFu, rm, 4));
            rm = fminf(rm, __shfl_xor_sync(0xFFFFFFFFu, rm, 8));
            if (tx == 0)
                atomicMax(&g_rowmin_key[b0 + row0 + i], ~__float_as_uint(rm));
        }

        // col-min partials over this thread's 8 rows
#pragma unroll
        for (int jj = 0; jj < 2; jj++) {
            float c = dist[0][jj];
#pragma unroll
            for (int i = 1; i < 8; i++) c = fminf(c, dist[i][jj]);
            cm[jb + jj] = c;
        }
    }

    // ---- col reduction: alias scratch into sm (tiles dead now) ----
    __syncthreads();
    unsigned int* cs = (unsigned int*)sm;   // [0..63] col keys, [64..71] red, [72] flag
    if (tid < TV) cs[tid] = 0u;
    __syncthreads();
#pragma unroll
    for (int j = 0; j < 4; j++)
        atomicMax(&cs[tx + 16 * j], ~__float_as_uint(cm[j]));
    __syncthreads();
    if (tid < TV)
        atomicMax(&g_colmin_key[v0 + tid], cs[tid]);

    // ---- last-block finalize ----
    __threadfence();
    if (tid == 0)
        cs[72] = (atomicAdd(&g_arrive, 1u) == (unsigned)(NBLOCKS - 1)) ? 1u : 0u;
    __syncthreads();
    if (cs[72] == 0u) return;

    float s1 = 0.f, s2 = 0.f;
    for (int i = tid; i < V_TOTAL; i += 128)
        s1 += __uint_as_float(~__ldcg(&g_colmin_key[i]));
    for (int i = tid; i < B_TOTAL; i += 128)
        s2 += __uint_as_float(~__ldcg(&g_rowmin_key[i]));
#pragma unroll
    for (int o = 16; o > 0; o >>= 1) {
        s1 += __shfl_xor_sync(0xFFFFFFFFu, s1, o);
        s2 += __shfl_xor_sync(0xFFFFFFFFu, s2, o);
    }
    float* red = (float*)(cs + 64);
    int wid = tid >> 5;
    if ((tid & 31) == 0) { red[wid] = s1; red[4 + wid] = s2; }
    __syncthreads();
    if (tid == 0) {
        float r1 = red[0] + red[1] + red[2] + red[3];
        float r2 = red[4] + red[5] + red[6] + red[7];
        out[(size_t)B_TOTAL * V_TOTAL]     = r1 / (float)V_TOTAL;
        out[(size_t)B_TOTAL * V_TOTAL + 1] = r2 / (float)B_TOTAL;
        g_arrive = 0u;
    }
    for (int i = tid; i < B_TOTAL; i += 128) g_rowmin_key[i] = 0u;
    for (int i = tid; i < V_TOTAL; i += 128) g_colmin_key[i] = 0u;
}

extern "C" void kernel_launch(void* const* d_in, const int* in_sizes, int n_in,
                              void* d_out, int out_size) {
    (void)in_sizes; (void)n_in; (void)out_size;
    const float* x = (const float*)d_in[0];
    const float* p = (const float*)d_in[1];
    float* out = (float*)d_out;

    dim3 grid(V_TOTAL / TV, B_TOTAL / TB);   // (16, 64) = 1024 CTAs, single wave
    dist_fused<<<grid, 128>>>(x, p, out);
}

// round 5
// speedup vs baseline: 1.0068x; 1.0068x over previous
#include <cuda_runtime.h>

#define B_TOTAL 4096
#define V_TOTAL 1024
#define DD 64
#define TB 64
#define TV 32
#define NBLOCKS ((B_TOTAL / TB) * (V_TOTAL / TV))

// Zero-initialized scratch. Min stored as key = ~bits(value); dist >= 0 so bit
// order == value order, atomicMax(key) == min(value), 0 is the identity.
// Last block resets everything to 0 -> graph-replay safe.
__device__ unsigned int g_rowmin_key[B_TOTAL];
__device__ unsigned int g_colmin_key[V_TOTAL];
__device__ unsigned int g_arrive;

typedef unsigned long long ull;

// acc += |a + b| (b pre-negated), packed f32x2, single asm region.
__device__ __forceinline__ void l1acc(ull& acc, ull a, ull b) {
    asm("{\n\t"
        ".reg .b64 d;\n\t"
        "add.rn.f32x2 d, %1, %2;\n\t"
        "and.b64 d, d, 0x7FFFFFFF7FFFFFFF;\n\t"
        "add.rn.f32x2 %0, %0, d;\n\t"
        "}"
        : "+l"(acc) : "l"(a), "l"(b));
}

__global__ __launch_bounds__(128, 7)
void dist_fused(const float* __restrict__ x, const float* __restrict__ p,
                float* __restrict__ out) {
    // 24 KB: sm[0..2047]      x pairs  XS(kk,row) = sm[kk*64 + row]
    //        sm[2048..3071]   p pairs  PS(kk,tx,j) = sm[2048 + kk*32 + tx*2 + j]
    //                         (j-interleaved so one LDS.128 covers v=tx, v=tx+16)
    __shared__ ull sm[3072];

    const int tid = threadIdx.x;
    const int b0 = blockIdx.y * TB;
    const int v0 = blockIdx.x * TV;

    // ---- prologue ----
    if (tid < 64) {
        // one x row per thread
        const float4* __restrict__ xr4 = (const float4*)(x + (size_t)(b0 + tid) * DD);
#pragma unroll
        for (int c4 = 0; c4 < 16; c4++) {
            float4 v = xr4[c4];
            int kk = c4 * 2;
            *(float2*)&sm[kk * 64 + tid]       = make_float2(v.x, v.y);
            *(float2*)&sm[(kk + 1) * 64 + tid] = make_float2(v.z, v.w);
        }
    } else {
        // p tile: 32 rows, two threads per row (half-row each), negated + interleaved
        int t = tid - 64;
        int r = t & 31;          // v row
        int half = t >> 5;       // 0/1
        int lane16 = r & 15, jslot = r >> 4;
        const float4* __restrict__ pr4 = (const float4*)(p + (size_t)(v0 + r) * DD);
#pragma unroll
        for (int c4i = 0; c4i < 8; c4i++) {
            int c4 = half * 8 + c4i;
            float4 v = pr4[c4];
            int kk = c4 * 2;
            *(float2*)&sm[2048 + kk * 32 + lane16 * 2 + jslot]       = make_float2(-v.x, -v.y);
            *(float2*)&sm[2048 + (kk + 1) * 32 + lane16 * 2 + jslot] = make_float2(-v.z, -v.w);
        }
    }
    __syncthreads();

    const int tx = tid & 15;    // v = tx (j=0), tx+16 (j=1)
    const int ty = tid >> 4;    // rows ty*8 .. ty*8+7
    const int row0 = ty * 8;

    ull acc[8][2];
#pragma unroll
    for (int i = 0; i < 8; i++) { acc[i][0] = 0ull; acc[i][1] = 0ull; }

    const ull* __restrict__ xp = &sm[row0];
    const ull* __restrict__ pp = &sm[2048 + tx * 2];

#pragma unroll 4
    for (int kk = 0; kk < 32; kk++) {
        // both v pairs in one LDS.128
        ulonglong2 P = *(const ulonglong2*)(pp + kk * 32);
        // two rows per LDS.128
        ulonglong2 X0 = *(const ulonglong2*)(xp + kk * 64 + 0);
        ulonglong2 X1 = *(const ulonglong2*)(xp + kk * 64 + 2);
        ulonglong2 X2 = *(const ulonglong2*)(xp + kk * 64 + 4);
        ulonglong2 X3 = *(const ulonglong2*)(xp + kk * 64 + 6);

        l1acc(acc[0][0], X0.x, P.x);  l1acc(acc[0][1], X0.x, P.y);
        l1acc(acc[1][0], X0.y, P.x);  l1acc(acc[1][1], X0.y, P.y);
        l1acc(acc[2][0], X1.x, P.x);  l1acc(acc[2][1], X1.x, P.y);
        l1acc(acc[3][0], X1.y, P.x);  l1acc(acc[3][1], X1.y, P.y);
        l1acc(acc[4][0], X2.x, P.x);  l1acc(acc[4][1], X2.x, P.y);
        l1acc(acc[5][0], X2.y, P.x);  l1acc(acc[5][1], X2.y, P.y);
        l1acc(acc[6][0], X3.x, P.x);  l1acc(acc[6][1], X3.x, P.y);
        l1acc(acc[7][0], X3.y, P.x);  l1acc(acc[7][1], X3.y, P.y);
    }

    // ---- horizontal pair sums ----
    float dist[8][2];
#pragma unroll
    for (int i = 0; i < 8; i++)
#pragma unroll
        for (int jj = 0; jj < 2; jj++) {
            ull a = acc[i][jj];
            float lo = __uint_as_float((unsigned)(a & 0xFFFFFFFFull));
            float hi = __uint_as_float((unsigned)(a >> 32));
            dist[i][jj] = lo + hi;
        }

    // ---- write distances (two 64B segments per row) ----
#pragma unroll
    for (int i = 0; i < 8; i++) {
        size_t base = (size_t)(b0 + row0 + i) * V_TOTAL + v0;
        out[base + tx]      = dist[i][0];
        out[base + tx + 16] = dist[i][1];
    }

    // ---- row mins over this v-tile: butterfly over 16 tx lanes ----
#pragma unroll
    for (int i = 0; i < 8; i++) {
        float rm = fminf(dist[i][0], dist[i][1]);
        rm = fminf(rm, __shfl_xor_sync(0xFFFFFFFFu, rm, 1));
        rm = fminf(rm, __shfl_xor_sync(0xFFFFFFFFu, rm, 2));
        rm = fminf(rm, __shfl_xor_sync(0xFFFFFFFFu, rm, 4));
        rm = fminf(rm, __shfl_xor_sync(0xFFFFFFFFu, rm, 8));
        if (tx == 0)
            atomicMax(&g_rowmin_key[b0 + row0 + i], ~__float_as_uint(rm));
    }

    // ---- col mins over this b-tile ----
    float cm0 = dist[0][0], cm1 = dist[0][1];
#pragma unroll
    for (int i = 1; i < 8; i++) {
        cm0 = fminf(cm0, dist[i][0]);
        cm1 = fminf(cm1, dist[i][1]);
    }
    __syncthreads();
    unsigned int* cs = (unsigned int*)sm;   // [0..31] col keys, [64..71] red, [72] flag
    if (tid < TV) cs[tid] = 0u;
    __syncthreads();
    atomicMax(&cs[tx],      ~__float_as_uint(cm0));
    atomicMax(&cs[tx + 16], ~__float_as_uint(cm1));
    __syncthreads();
    if (tid < TV)
        atomicMax(&g_colmin_key[v0 + tid], cs[tid]);

    // ---- last-block finalize ----
    __threadfence();
    if (tid == 0)
        cs[72] = (atomicAdd(&g_arrive, 1u) == (unsigned)(NBLOCKS - 1)) ? 1u : 0u;
    __syncthreads();
    if (cs[72] == 0u) return;

    float s1 = 0.f, s2 = 0.f;
    for (int i = tid; i < V_TOTAL; i += 128)
        s1 += __uint_as_float(~__ldcg(&g_colmin_key[i]));
    for (int i = tid; i < B_TOTAL; i += 128)
        s2 += __uint_as_float(~__ldcg(&g_rowmin_key[i]));
#pragma unroll
    for (int o = 16; o > 0; o >>= 1) {
        s1 += __shfl_xor_sync(0xFFFFFFFFu, s1, o);
        s2 += __shfl_xor_sync(0xFFFFFFFFu, s2, o);
    }
    float* red = (float*)(cs + 64);
    int wid = tid >> 5;
    if ((tid & 31) == 0) { red[wid] = s1; red[4 + wid] = s2; }
    __syncthreads();
    if (tid == 0) {
        float r1 = red[0] + red[1] + red[2] + red[3];
        float r2 = red[4] + red[5] + red[6] + red[7];
        out[(size_t)B_TOTAL * V_TOTAL]     = r1 / (float)V_TOTAL;
        out[(size_t)B_TOTAL * V_TOTAL + 1] = r2 / (float)B_TOTAL;
        g_arrive = 0u;
    }
    for (int i = tid; i < B_TOTAL; i += 128) g_rowmin_key[i] = 0u;
    for (int i = tid; i < V_TOTAL; i += 128) g_colmin_key[i] = 0u;
}

extern "C" void kernel_launch(void* const* d_in, const int* in_sizes, int n_in,
                              void* d_out, int out_size) {
    (void)in_sizes; (void)n_in; (void)out_size;
    const float* x = (const float*)d_in[0];
    const float* p = (const float*)d_in[1];
    float* out = (float*)d_out;

    dim3 grid(V_TOTAL / TV, B_TOTAL / TB);   // (32, 64) = 2048 CTAs
    dist_fused<<<grid, 128>>>(x, p, out);
}